// round 2
// baseline (speedup 1.0000x reference)
#include <cuda_runtime.h>
#include <cuda_bf16.h>

#define NTIME  4096
#define NBATCH 4096
#define NEXTRA 256
#define CS     8                    // coarse sampling stride (rows)
#define NS     (NTIME / CS)         // 512 coarse rows

// Compact coarse index: coarse[j][b] = times[j*CS][b]. 8 MB, L2-resident.
__device__ float g_coarse[NS * NBATCH];

// Phase 1: coalesced float4 strided-row copy into the coarse index.
__global__ __launch_bounds__(256)
void build_coarse_kernel(const float* __restrict__ times)
{
    const int idx = blockIdx.x * blockDim.x + threadIdx.x;   // over NS*NBATCH/4
    const int W = NBATCH / 4;
    if (idx >= NS * W) return;
    const int j  = idx / W;
    const int b4 = idx - j * W;
    const float4* src = (const float4*)times;
    float4* dst = (float4*)g_coarse;
    dst[j * W + b4] = src[(size_t)(j * CS) * W + b4];
}

// Phase 2: coarse interpolation search (L2-hot) -> 8-wide bracket ->
// fine interpolation search (1-2 DRAM probes) -> interpolate.
__global__ __launch_bounds__(256, 8)
void ts_interp_kernel(const float* __restrict__ times,
                      const float* __restrict__ values,
                      const float* __restrict__ t,
                      float* __restrict__ out)
{
    const int gid = blockIdx.x * blockDim.x + threadIdx.x;
    if (gid >= NEXTRA * NBATCH) return;
    const int b = gid & (NBATCH - 1);

    const float tq = __ldg(&t[gid]);
    const float ta = __ldg(&times[b]);                                   // times[0, b]
    const float tb = __ldg(&times[(size_t)(NTIME - 1) * NBATCH + b]);    // times[NTIME-1, b]

    // counts == 0 or counts == NTIME -> gi = 0 -> torch wrap to last segment.
    if (tq < ta || tq >= tb) {
        const float t1 = tb;
        const float t0 = __ldg(&times [(size_t)(NTIME - 2) * NBATCH + b]);
        const float v1 = __ldg(&values[(size_t)(NTIME - 1) * NBATCH + b]);
        const float v0 = __ldg(&values[(size_t)(NTIME - 2) * NBATCH + b]);
        const float s  = (v1 - v0) / (t1 - t0);
        out[gid] = v1 + s * (tq - t1);
        return;
    }

    // ---- Coarse stage: largest j in [0, NS-1] with coarse[j] <= tq. ----
    // Invariant: coarse[jlo] <= tq < (jhi==NS ? tb : coarse[jhi]).
    int   jlo = 0, jhi = NS;
    float ctlo = ta, cthi = tb;          // coarse[0] == times[0] == ta
    int citer = 0;
    while (jhi - jlo > 1) {
        int jm;
        if (citer < 5) {
            const float f = (tq - ctlo) / (cthi - ctlo);
            jm = jlo + 1 + (int)(f * (float)(jhi - jlo - 1));
            jm = max(jlo + 1, min(jm, jhi - 1));
        } else {
            jm = (jlo + jhi) >> 1;
        }
        const float cm = g_coarse[(size_t)jm * NBATCH + b];
        if (cm <= tq) { jlo = jm; ctlo = cm; }
        else          { jhi = jm; cthi = cm; }
        ++citer;
    }

    // ---- Fine stage inside [jlo*CS, min(jlo*CS+CS, NTIME-1)] ----
    int   lo = jlo * CS;
    int   hi = (jhi == NS) ? (NTIME - 1) : jhi * CS;
    float tlo = ctlo, thi = cthi;        // == times[lo], times[hi] (exact copies)

    int iter = 0;
    while (hi - lo > 1) {
        int mid;
        if (iter < 3) {
            const float f = (tq - tlo) / (thi - tlo);
            mid = lo + 1 + (int)(f * (float)(hi - lo - 1));
            mid = max(lo + 1, min(mid, hi - 1));
        } else {
            mid = (lo + hi) >> 1;
        }
        const float tm = __ldg(&times[(size_t)mid * NBATCH + b]);
        if (tm <= tq) { lo = mid; tlo = tm; }   // '<=' == side='right'
        else          { hi = mid; thi = tm; }
        ++iter;
    }

    const float v0 = __ldg(&values[(size_t)lo * NBATCH + b]);
    const float v1 = __ldg(&values[(size_t)hi * NBATCH + b]);
    const float s  = (v1 - v0) / (thi - tlo);
    out[gid] = v0 + s * (tq - tlo);
}

extern "C" void kernel_launch(void* const* d_in, const int* in_sizes, int n_in,
                              void* d_out, int out_size)
{
    const float* times  = nullptr;
    const float* values = nullptr;
    const float* tq     = nullptr;
    for (int i = 0; i < n_in; ++i) {
        if (in_sizes[i] == NEXTRA * NBATCH && tq == nullptr) {
            tq = (const float*)d_in[i];
        } else if (times == nullptr) {
            times = (const float*)d_in[i];
        } else if (values == nullptr) {
            values = (const float*)d_in[i];
        }
    }

    float* out = (float*)d_out;

    {   // Phase 1: build coarse index (coalesced, ~16 MB traffic)
        const int n   = NS * NBATCH / 4;
        const int thr = 256;
        build_coarse_kernel<<<(n + thr - 1) / thr, thr>>>(times);
    }
    {   // Phase 2: search + interpolate
        const int total = NEXTRA * NBATCH;
        const int thr   = 256;
        ts_interp_kernel<<<(total + thr - 1) / thr, thr>>>(times, values, tq, out);
    }
}